// round 2
// baseline (speedup 1.0000x reference)
#include <cuda_runtime.h>

// Problem constants (fixed by the dataset: midis_out is (16, 11, 65536) fp32)
#define NB      16
#define NI      11
#define NT      65536
#define LSTLEN  64
#define CHUNK   512                 // time steps per CTA
#define NTB     (CHUNK / LSTLEN)    // 8 time-blocks per CTA
#define THREADS 256
#define NWARP   (THREADS / 32)
#define NCHUNK  (NT / CHUNK)        // 128 chunks per (b)
#define VEC4    (NI * CHUNK / 4)    // 1408 float4 per CTA tile

__global__ __launch_bounds__(THREADS)
void multiply_sparsemax_kernel(const float* __restrict__ in,
                               float* __restrict__ out)
{
    __shared__ float xs[NI * CHUNK];       // 22528 B tile
    __shared__ float tau_time[NI * NTB];   // 88 taus (per inst, per 64-block)
    __shared__ float tau_inst[CHUNK];      // 512 taus (per time step)

    const int tid  = threadIdx.x;
    const int wid  = tid >> 5;
    const int lane = tid & 31;

    const int blk = blockIdx.x;
    const int b   = blk / NCHUNK;
    const int c   = blk % NCHUNK;
    const long base = (long)b * NI * NT + (long)c * CHUNK;

    // ---- Load tile: 11 rows x 512 contiguous floats, float4-coalesced ----
    #pragma unroll 2
    for (int idx = tid; idx < VEC4; idx += THREADS) {
        const int i  = idx / (CHUNK / 4);
        const int t4 = idx % (CHUNK / 4);
        float4 v = *((const float4*)(in + base + (long)i * NT) + t4);
        *(float4*)(xs + i * CHUNK + t4 * 4) = v;
    }
    __syncthreads();

    // ---- Phase A: sparsemax tau over 64-length time blocks (warp-per-block) ----
    // Michelot fixed-point: tau <- (sum_{z>tau} z - 1)/count. The support set
    // {z > tau} only shrinks (tau is non-decreasing), so the loop terminates
    // at the exact sparsemax tau; typically 2-6 iterations for N(0,1) data.
    for (int task = wid; task < NI * NTB; task += NWARP) {
        const int i  = task / NTB;
        const int tb = task % NTB;
        const float2 v = *(const float2*)(xs + i * CHUNK + tb * LSTLEN + lane * 2);
        const float a0 = v.x, a1 = v.y;

        float s = a0 + a1;
        #pragma unroll
        for (int o = 16; o; o >>= 1) s += __shfl_xor_sync(0xFFFFFFFFu, s, o);

        float tau = (s - 1.0f) * (1.0f / 64.0f);
        int k = 64;

        #pragma unroll 1
        for (int it = 0; it < 64; ++it) {
            const bool p0 = a0 > tau, p1 = a1 > tau;
            const int kn = __popc(__ballot_sync(0xFFFFFFFFu, p0))
                         + __popc(__ballot_sync(0xFFFFFFFFu, p1));
            if (kn >= k) break;               // support stable -> converged
            float ss = (p0 ? a0 : 0.0f) + (p1 ? a1 : 0.0f);
            #pragma unroll
            for (int o = 16; o; o >>= 1) ss += __shfl_xor_sync(0xFFFFFFFFu, ss, o);
            tau = (ss - 1.0f) / (float)kn;
            k = kn;
        }
        if (lane == 0) tau_time[i * NTB + tb] = tau;
    }

    // ---- Phase B: sparsemax tau over the 11 instruments (thread-per-t) ----
    #pragma unroll 1
    for (int t = tid; t < CHUNK; t += THREADS) {
        float z[NI];
        float s = 0.0f;
        #pragma unroll
        for (int i = 0; i < NI; ++i) { z[i] = xs[i * CHUNK + t]; s += z[i]; }

        float tau = (s - 1.0f) * (1.0f / (float)NI);
        int k = NI;

        #pragma unroll 1
        for (int it = 0; it < NI; ++it) {
            float ss = 0.0f; int cc = 0;
            #pragma unroll
            for (int i = 0; i < NI; ++i)
                if (z[i] > tau) { ss += z[i]; ++cc; }
            if (cc >= k) break;
            tau = (ss - 1.0f) / (float)cc;
            k = cc;
        }
        tau_inst[t] = tau;
    }
    __syncthreads();

    // ---- Phase C: fused epilogue, float4 writes ----
    #pragma unroll 2
    for (int idx = tid; idx < VEC4; idx += THREADS) {
        const int i  = idx / (CHUNK / 4);
        const int t4 = idx % (CHUNK / 4);
        const int t  = t4 * 4;
        const float4 v  = *(const float4*)(xs + i * CHUNK + t);
        const float tt  = tau_time[i * NTB + (t >> 6)];
        float4 r;
        r.x = fmaxf(v.x - tau_inst[t + 0], 0.0f) * fmaxf(v.x - tt, 0.0f);
        r.y = fmaxf(v.y - tau_inst[t + 1], 0.0f) * fmaxf(v.y - tt, 0.0f);
        r.z = fmaxf(v.z - tau_inst[t + 2], 0.0f) * fmaxf(v.z - tt, 0.0f);
        r.w = fmaxf(v.w - tau_inst[t + 3], 0.0f) * fmaxf(v.w - tt, 0.0f);
        *((float4*)(out + base + (long)i * NT) + t4) = r;
    }
}

extern "C" void kernel_launch(void* const* d_in, const int* in_sizes, int n_in,
                              void* d_out, int out_size)
{
    const float* in = (const float*)d_in[0];
    float* out = (float*)d_out;
    const int grid = NB * NCHUNK;   // 2048 CTAs
    multiply_sparsemax_kernel<<<grid, THREADS>>>(in, out);
}

// round 3
// speedup vs baseline: 1.8317x; 1.8317x over previous
#include <cuda_runtime.h>

// Problem constants (fixed: midis_out is (16, 11, 65536) fp32, LST=64)
#define NB      16
#define NI      11
#define NT      65536
#define LSTLEN  64
#define CHUNK   512
#define NTB     (CHUNK / LSTLEN)    // 8 time-blocks per CTA
#define THREADS 256
#define NWARP   (THREADS / 32)
#define NCHUNK  (NT / CHUNK)        // 128
#define VEC4    (NI * CHUNK / 4)    // 1408 float4 per tile
#define NTASK   (NI * NTB)          // 88 time-block sparsemax tasks
#define NGRP    (NTASK / 4)         // 22 groups of 4 tasks

__global__ __launch_bounds__(THREADS)
void multiply_sparsemax_kernel(const float* __restrict__ in,
                               float* __restrict__ out)
{
    __shared__ float xs[NI * CHUNK];       // 22528 B tile
    __shared__ float tau_time[NTASK];      // per (inst, 64-block)
    __shared__ float tau_inst[CHUNK];      // per time step

    const int tid  = threadIdx.x;
    const int wid  = tid >> 5;
    const int lane = tid & 31;

    const int b = blockIdx.x / NCHUNK;
    const int c = blockIdx.x % NCHUNK;
    const long base = (long)b * NI * NT + (long)c * CHUNK;

    // ---- Load tile: 11 rows x 512 floats, float4-coalesced ----
    #pragma unroll
    for (int idx = tid; idx < VEC4; idx += THREADS) {
        const int i  = idx >> 7;          // / (CHUNK/4)
        const int t4 = idx & 127;
        *(float4*)(xs + i * CHUNK + t4 * 4) =
            *((const float4*)(in + base + (long)i * NT) + t4);
    }
    __syncthreads();

    // ---- Phase A: sparsemax tau over 64-length time blocks ----
    // 4 tasks per warp concurrently: 8-lane segment per task, 8 elems/lane.
    // Michelot fixed-point with safe warm start: tau* >= max(z) - 1 always
    // (since max output <= sum outputs = 1), so S0 = {z > max-1} contains the
    // support and the iteration converges monotonically in ~2-3 steps.
    {
        const int seg = lane >> 3;        // 0..3 : which task in the group
        const int sl  = lane & 7;         // 0..7 : sub-lane within task
        for (int g = wid; g < NGRP; g += NWARP) {
            const int task = g * 4 + seg;            // = i*NTB + tb
            const float* p = xs + (task >> 3) * CHUNK + (task & 7) * LSTLEN + sl * 8;
            const float4 v0 = *(const float4*)p;
            const float4 v1 = *(const float4*)(p + 4);
            const float z0 = v0.x, z1 = v0.y, z2 = v0.z, z3 = v0.w;
            const float z4 = v1.x, z5 = v1.y, z6 = v1.z, z7 = v1.w;

            float m = fmaxf(fmaxf(fmaxf(z0, z1), fmaxf(z2, z3)),
                            fmaxf(fmaxf(z4, z5), fmaxf(z6, z7)));
            #pragma unroll
            for (int o = 4; o; o >>= 1)
                m = fmaxf(m, __shfl_xor_sync(0xFFFFFFFFu, m, o));

            float tau = m - 1.0f;   // threshold only; first iter replaces it
            int   k   = 65;         // sentinel > d
            bool  done = false;

            #pragma unroll 1
            for (int it = 0; it < 64; ++it) {
                float ss = 0.0f; int cc = 0;
                if (z0 > tau) { ss += z0; ++cc; }
                if (z1 > tau) { ss += z1; ++cc; }
                if (z2 > tau) { ss += z2; ++cc; }
                if (z3 > tau) { ss += z3; ++cc; }
                if (z4 > tau) { ss += z4; ++cc; }
                if (z5 > tau) { ss += z5; ++cc; }
                if (z6 > tau) { ss += z6; ++cc; }
                if (z7 > tau) { ss += z7; ++cc; }
                float cf = (float)cc;
                #pragma unroll
                for (int o = 4; o; o >>= 1) {
                    ss += __shfl_xor_sync(0xFFFFFFFFu, ss, o);
                    cf += __shfl_xor_sync(0xFFFFFFFFu, cf, o);
                }
                const int kn = (int)cf;
                if (kn >= k) done = true;            // support stable -> tau final
                if (!done) {
                    tau = __fdividef(ss - 1.0f, cf);
                    k = kn;
                }
                if (__all_sync(0xFFFFFFFFu, done)) break;  // uniform exit
            }
            if (sl == 0) tau_time[task] = tau;
        }
    }

    // ---- Phase B: sparsemax tau over the 11 instruments, 2 columns/thread ----
    {
        const int t0 = tid * 2;
        float za[NI], zb[NI];
        float ma = -1e30f, mb = -1e30f;
        #pragma unroll
        for (int i = 0; i < NI; ++i) {
            const float2 v = *(const float2*)(xs + i * CHUNK + t0);
            za[i] = v.x; zb[i] = v.y;
            ma = fmaxf(ma, v.x); mb = fmaxf(mb, v.y);
        }
        float ta = ma - 1.0f, tb = mb - 1.0f;
        int   ka = 12,        kb = 12;        // sentinel > d
        bool  da = false,     db = false;

        #pragma unroll 1
        for (int it = 0; it < 12; ++it) {
            if (!da) {
                float ss = 0.0f; int cc = 0;
                #pragma unroll
                for (int i = 0; i < NI; ++i)
                    if (za[i] > ta) { ss += za[i]; ++cc; }
                if (cc >= ka) da = true;
                else { ta = __fdividef(ss - 1.0f, (float)cc); ka = cc; }
            }
            if (!db) {
                float ss = 0.0f; int cc = 0;
                #pragma unroll
                for (int i = 0; i < NI; ++i)
                    if (zb[i] > tb) { ss += zb[i]; ++cc; }
                if (cc >= kb) db = true;
                else { tb = __fdividef(ss - 1.0f, (float)cc); kb = cc; }
            }
            if (da && db) break;
        }
        *(float2*)(tau_inst + t0) = make_float2(ta, tb);
    }
    __syncthreads();

    // ---- Phase C: fused epilogue, float4 in/out ----
    #pragma unroll
    for (int idx = tid; idx < VEC4; idx += THREADS) {
        const int i  = idx >> 7;
        const int t4 = idx & 127;
        const int t  = t4 * 4;
        const float4 v  = *(const float4*)(xs + i * CHUNK + t);
        const float4 ti = *(const float4*)(tau_inst + t);
        const float  tt = tau_time[i * NTB + (t >> 6)];
        float4 r;
        r.x = fmaxf(v.x - ti.x, 0.0f) * fmaxf(v.x - tt, 0.0f);
        r.y = fmaxf(v.y - ti.y, 0.0f) * fmaxf(v.y - tt, 0.0f);
        r.z = fmaxf(v.z - ti.z, 0.0f) * fmaxf(v.z - tt, 0.0f);
        r.w = fmaxf(v.w - ti.w, 0.0f) * fmaxf(v.w - tt, 0.0f);
        *((float4*)(out + base + (long)i * NT) + t4) = r;
    }
}

extern "C" void kernel_launch(void* const* d_in, const int* in_sizes, int n_in,
                              void* d_out, int out_size)
{
    const float* in = (const float*)d_in[0];
    float* out = (float*)d_out;
    multiply_sparsemax_kernel<<<NB * NCHUNK, THREADS>>>(in, out);
}

// round 4
// speedup vs baseline: 2.3032x; 1.2574x over previous
#include <cuda_runtime.h>

// Problem constants (fixed: midis_out is (16, 11, 65536) fp32, LST=64)
#define NB      16
#define NI      11
#define NT      65536
#define LSTLEN  64
#define CHUNK   512
#define NTB     (CHUNK / LSTLEN)    // 8 time-blocks per CTA
#define THREADS 256
#define NWARP   (THREADS / 32)
#define NCHUNK  (NT / CHUNK)        // 128
#define VEC4    (NI * CHUNK / 4)    // 1408 float4 per tile
#define NTASK   (NI * NTB)          // 88 time-block tasks
#define NGRP    (NTASK / 4)         // 22 groups of 4 tasks

__device__ __forceinline__ void ce(float& a, float& b) {
    const float lo = fminf(a, b), hi = fmaxf(a, b);
    a = lo; b = hi;
}

// Optimal 11-input sorting network (35 CE, depth 8), ascending.
__device__ __forceinline__ void sort11(float z[NI]) {
    ce(z[0],z[9]); ce(z[1],z[6]); ce(z[2],z[4]); ce(z[3],z[7]); ce(z[5],z[8]);
    ce(z[0],z[1]); ce(z[3],z[5]); ce(z[4],z[10]); ce(z[6],z[9]); ce(z[7],z[8]);
    ce(z[1],z[3]); ce(z[2],z[5]); ce(z[4],z[7]); ce(z[8],z[10]);
    ce(z[0],z[4]); ce(z[1],z[2]); ce(z[3],z[7]); ce(z[5],z[9]); ce(z[6],z[8]);
    ce(z[0],z[1]); ce(z[2],z[6]); ce(z[4],z[5]); ce(z[7],z[8]); ce(z[9],z[10]);
    ce(z[2],z[4]); ce(z[3],z[6]); ce(z[5],z[7]); ce(z[8],z[9]);
    ce(z[1],z[2]); ce(z[3],z[4]); ce(z[5],z[6]); ce(z[7],z[8]);
    ce(z[2],z[3]); ce(z[4],z[5]); ce(z[6],z[7]);
}

// Exact sparsemax tau over 11 values (destroys z). Reference formulation:
// sorted descending, k_z = #{k : 1 + k*z_(k) > csum_k}, tau = (csum_{k_z}-1)/k_z.
// Support test is prefix-monotone -> last passing k wins (select chain).
__device__ __forceinline__ float sparsemax11_tau(float z[NI]) {
    sort11(z);
    float c = 0.0f, tau = 0.0f;
    #pragma unroll
    for (int k = 1; k <= NI; ++k) {
        const float zk = z[NI - k];          // k-th largest
        c += zk;
        const float cand = (c - 1.0f) * (1.0f / (float)k);
        const bool sup = fmaf((float)k, zk, 1.0f) > c;
        tau = (k == 1) ? cand : (sup ? cand : tau);
    }
    return tau;
}

__global__ __launch_bounds__(THREADS)
void multiply_sparsemax_kernel(const float* __restrict__ in,
                               float* __restrict__ out)
{
    __shared__ float xs[NI * CHUNK];       // 22528 B tile
    __shared__ float tau_time[NTASK];      // per (inst, 64-block)

    const int tid  = threadIdx.x;
    const int wid  = tid >> 5;
    const int lane = tid & 31;

    const int b = blockIdx.x / NCHUNK;
    const int c = blockIdx.x % NCHUNK;
    const unsigned base = (unsigned)(b * NI) * NT + (unsigned)(c * CHUNK);

    // ---- Load tile: 11 rows x 512 floats, float4-coalesced ----
    #pragma unroll
    for (int idx = tid; idx < VEC4; idx += THREADS) {
        const int i  = idx >> 7;
        const int t4 = idx & 127;
        *(float4*)(xs + i * CHUNK + t4 * 4) =
            *((const float4*)(in + base + (unsigned)(i * NT)) + t4);
    }
    __syncthreads();

    // ---- Phase A: tau over 64-length time blocks ----
    // 4 tasks/warp (8-lane segments, 8 elems/lane). Michelot from the safe
    // warm start tau0 = max-1 (tau* >= max-1 always). Updates are idempotent
    // at the fixed point, so 3 unconditional iterations + a checked guard
    // loop (usually exits on first check) is exact and branch-light.
    {
        const int seg = lane >> 3;
        const int sl  = lane & 7;
        for (int g = wid; g < NGRP; g += NWARP) {
            const int task = g * 4 + seg;
            const float* p = xs + (task >> 3) * CHUNK + (task & 7) * LSTLEN + sl * 8;
            const float4 v0 = *(const float4*)p;
            const float4 v1 = *(const float4*)(p + 4);
            const float z0 = v0.x, z1 = v0.y, z2 = v0.z, z3 = v0.w;
            const float z4 = v1.x, z5 = v1.y, z6 = v1.z, z7 = v1.w;

            float m = fmaxf(fmaxf(fmaxf(z0, z1), fmaxf(z2, z3)),
                            fmaxf(fmaxf(z4, z5), fmaxf(z6, z7)));
            #pragma unroll
            for (int o = 4; o; o >>= 1)
                m = fmaxf(m, __shfl_xor_sync(0xFFFFFFFFu, m, o));

            float tau = m - 1.0f;
            float cf  = 0.0f;

            #pragma unroll
            for (int it = 0; it < 3; ++it) {
                float ss = 0.0f; cf = 0.0f;
                if (z0 > tau) { ss += z0; cf += 1.0f; }
                if (z1 > tau) { ss += z1; cf += 1.0f; }
                if (z2 > tau) { ss += z2; cf += 1.0f; }
                if (z3 > tau) { ss += z3; cf += 1.0f; }
                if (z4 > tau) { ss += z4; cf += 1.0f; }
                if (z5 > tau) { ss += z5; cf += 1.0f; }
                if (z6 > tau) { ss += z6; cf += 1.0f; }
                if (z7 > tau) { ss += z7; cf += 1.0f; }
                #pragma unroll
                for (int o = 4; o; o >>= 1) {
                    ss += __shfl_xor_sync(0xFFFFFFFFu, ss, o);
                    cf += __shfl_xor_sync(0xFFFFFFFFu, cf, o);
                }
                tau = __fdividef(ss - 1.0f, cf);
            }

            int k = (int)cf;
            #pragma unroll 1
            for (;;) {
                float ss = 0.0f, c2 = 0.0f;
                if (z0 > tau) { ss += z0; c2 += 1.0f; }
                if (z1 > tau) { ss += z1; c2 += 1.0f; }
                if (z2 > tau) { ss += z2; c2 += 1.0f; }
                if (z3 > tau) { ss += z3; c2 += 1.0f; }
                if (z4 > tau) { ss += z4; c2 += 1.0f; }
                if (z5 > tau) { ss += z5; c2 += 1.0f; }
                if (z6 > tau) { ss += z6; c2 += 1.0f; }
                if (z7 > tau) { ss += z7; c2 += 1.0f; }
                #pragma unroll
                for (int o = 4; o; o >>= 1) {
                    ss += __shfl_xor_sync(0xFFFFFFFFu, ss, o);
                    c2 += __shfl_xor_sync(0xFFFFFFFFu, c2, o);
                }
                const int kn = (int)c2;
                const bool conv = (kn >= k);         // support stable
                if (__all_sync(0xFFFFFFFFu, conv)) break;
                if (!conv) { tau = __fdividef(ss - 1.0f, c2); k = kn; }
            }
            if (sl == 0) tau_time[task] = tau;
        }
    }
    __syncthreads();

    // ---- Phase B+C fused: instrument sparsemax (sort-based, branch-free)
    //      + epilogue written straight to gmem ----
    {
        const int t0 = tid * 2;                  // 2 adjacent columns
        float za[NI], zb[NI];
        #pragma unroll
        for (int i = 0; i < NI; ++i) {
            const float2 v = *(const float2*)(xs + i * CHUNK + t0);
            za[i] = v.x; zb[i] = v.y;
        }
        const float ta  = sparsemax11_tau(za);   // destroys za
        const float tb2 = sparsemax11_tau(zb);   // destroys zb

        const int blkb = wid;                    // t0>>6 == tid>>5 (uniform/warp)
        const float* px = xs + t0;
        float* po = out + base + (unsigned)t0;
        #pragma unroll
        for (int i = 0; i < NI; ++i) {
            const float  tt = tau_time[i * NTB + blkb];  // broadcast LDS
            const float2 v  = *(const float2*)(px + i * CHUNK);
            float2 r;
            r.x = fmaxf(v.x - ta,  0.0f) * fmaxf(v.x - tt, 0.0f);
            r.y = fmaxf(v.y - tb2, 0.0f) * fmaxf(v.y - tt, 0.0f);
            *(float2*)(po + (unsigned)(i * NT)) = r;
        }
    }
}

extern "C" void kernel_launch(void* const* d_in, const int* in_sizes, int n_in,
                              void* d_out, int out_size)
{
    const float* in = (const float*)d_in[0];
    float* out = (float*)d_out;
    multiply_sparsemax_kernel<<<NB * NCHUNK, THREADS>>>(in, out);
}

// round 5
// speedup vs baseline: 2.3545x; 1.0223x over previous
#include <cuda_runtime.h>

// Problem constants (fixed: midis_out is (16, 11, 65536) fp32, LST=64)
#define NB      16
#define NI      11
#define NT      65536
#define LSTLEN  64
#define CHUNK   512
#define NTB     (CHUNK / LSTLEN)    // 8 time-blocks per CTA
#define THREADS 256
#define NWARP   (THREADS / 32)
#define NCHUNK  (NT / CHUNK)        // 128
#define VEC4    (NI * CHUNK / 4)    // 1408 float4 per tile
#define NTASK   (NI * NTB)          // 88 time-block tasks
#define NGRP    (NTASK / 4)         // 22 groups of 4 tasks

__device__ __forceinline__ void ce(float& a, float& b) {
    const float lo = fminf(a, b), hi = fmaxf(a, b);
    a = lo; b = hi;
}

// Optimal 11-input sorting network (35 CE, depth 8), ascending.
__device__ __forceinline__ void sort11(float z[NI]) {
    ce(z[0],z[9]); ce(z[1],z[6]); ce(z[2],z[4]); ce(z[3],z[7]); ce(z[5],z[8]);
    ce(z[0],z[1]); ce(z[3],z[5]); ce(z[4],z[10]); ce(z[6],z[9]); ce(z[7],z[8]);
    ce(z[1],z[3]); ce(z[2],z[5]); ce(z[4],z[7]); ce(z[8],z[10]);
    ce(z[0],z[4]); ce(z[1],z[2]); ce(z[3],z[7]); ce(z[5],z[9]); ce(z[6],z[8]);
    ce(z[0],z[1]); ce(z[2],z[6]); ce(z[4],z[5]); ce(z[7],z[8]); ce(z[9],z[10]);
    ce(z[2],z[4]); ce(z[3],z[6]); ce(z[5],z[7]); ce(z[8],z[9]);
    ce(z[1],z[2]); ce(z[3],z[4]); ce(z[5],z[6]); ce(z[7],z[8]);
    ce(z[2],z[3]); ce(z[4],z[5]); ce(z[6],z[7]);
}

// Exact sparsemax tau over 11 values (destroys z). Reference formulation:
// sorted descending, k_z = #{k : 1 + k*z_(k) > csum_k}, tau = (csum_{k_z}-1)/k_z.
// Support test is prefix-monotone -> last passing k wins (select chain).
__device__ __forceinline__ float sparsemax11_tau(float z[NI]) {
    sort11(z);
    float c   = z[NI - 1];               // k = 1: always in support
    float tau = c - 1.0f;
    #pragma unroll
    for (int k = 2; k <= NI; ++k) {
        const float zk = z[NI - k];      // k-th largest
        c += zk;
        const float cand = (c - 1.0f) * (1.0f / (float)k);
        const bool sup = fmaf((float)k, zk, 1.0f) > c;
        tau = sup ? cand : tau;
    }
    return tau;
}

__global__ __launch_bounds__(THREADS, 6)
void multiply_sparsemax_kernel(const float* __restrict__ in,
                               float* __restrict__ out)
{
    __shared__ float xs[NI * CHUNK];       // 22528 B tile
    __shared__ float tau_time[NTASK];      // per (inst, 64-block)

    const int tid  = threadIdx.x;
    const int wid  = tid >> 5;
    const int lane = tid & 31;

    const int b = blockIdx.x / NCHUNK;
    const int c = blockIdx.x % NCHUNK;
    const unsigned base = (unsigned)(b * NI) * NT + (unsigned)(c * CHUNK);

    // ---- Load tile: 11 rows x 512 floats, float4-coalesced ----
    #pragma unroll
    for (int idx = tid; idx < VEC4; idx += THREADS) {
        const int i  = idx >> 7;
        const int t4 = idx & 127;
        *(float4*)(xs + i * CHUNK + t4 * 4) =
            *((const float4*)(in + base + (unsigned)(i * NT)) + t4);
    }
    __syncthreads();

    // ---- Phase A: tau over 64-length time blocks ----
    // 4 tasks/warp (8-lane segments, 8 elems/lane). Michelot from the safe
    // warm start tau0 = max-1 (tau* >= max-1 always). Updates are idempotent
    // at the fixed point: 3 unconditional iterations + a checked guard loop
    // (usually exits on its first check) -> exact and branch-light.
    {
        const int seg = lane >> 3;
        const int sl  = lane & 7;
        for (int g = wid; g < NGRP; g += NWARP) {
            const int task = g * 4 + seg;
            const float* p = xs + (task >> 3) * CHUNK + (task & 7) * LSTLEN + sl * 8;
            const float4 v0 = *(const float4*)p;
            const float4 v1 = *(const float4*)(p + 4);
            const float z0 = v0.x, z1 = v0.y, z2 = v0.z, z3 = v0.w;
            const float z4 = v1.x, z5 = v1.y, z6 = v1.z, z7 = v1.w;

            float m = fmaxf(fmaxf(fmaxf(z0, z1), fmaxf(z2, z3)),
                            fmaxf(fmaxf(z4, z5), fmaxf(z6, z7)));
            #pragma unroll
            for (int o = 4; o; o >>= 1)
                m = fmaxf(m, __shfl_xor_sync(0xFFFFFFFFu, m, o));

            float tau = m - 1.0f;
            float cf  = 0.0f;

            #pragma unroll
            for (int it = 0; it < 3; ++it) {
                float ss = 0.0f; cf = 0.0f;
                if (z0 > tau) { ss += z0; cf += 1.0f; }
                if (z1 > tau) { ss += z1; cf += 1.0f; }
                if (z2 > tau) { ss += z2; cf += 1.0f; }
                if (z3 > tau) { ss += z3; cf += 1.0f; }
                if (z4 > tau) { ss += z4; cf += 1.0f; }
                if (z5 > tau) { ss += z5; cf += 1.0f; }
                if (z6 > tau) { ss += z6; cf += 1.0f; }
                if (z7 > tau) { ss += z7; cf += 1.0f; }
                #pragma unroll
                for (int o = 4; o; o >>= 1) {
                    ss += __shfl_xor_sync(0xFFFFFFFFu, ss, o);
                    cf += __shfl_xor_sync(0xFFFFFFFFu, cf, o);
                }
                tau = __fdividef(ss - 1.0f, cf);
            }

            int k = (int)cf;
            #pragma unroll 1
            for (;;) {
                float ss = 0.0f, c2 = 0.0f;
                if (z0 > tau) { ss += z0; c2 += 1.0f; }
                if (z1 > tau) { ss += z1; c2 += 1.0f; }
                if (z2 > tau) { ss += z2; c2 += 1.0f; }
                if (z3 > tau) { ss += z3; c2 += 1.0f; }
                if (z4 > tau) { ss += z4; c2 += 1.0f; }
                if (z5 > tau) { ss += z5; c2 += 1.0f; }
                if (z6 > tau) { ss += z6; c2 += 1.0f; }
                if (z7 > tau) { ss += z7; c2 += 1.0f; }
                #pragma unroll
                for (int o = 4; o; o >>= 1) {
                    ss += __shfl_xor_sync(0xFFFFFFFFu, ss, o);
                    c2 += __shfl_xor_sync(0xFFFFFFFFu, c2, o);
                }
                const int kn = (int)c2;
                const bool conv = (kn >= k);         // support stable
                if (__all_sync(0xFFFFFFFFu, conv)) break;
                if (!conv) { tau = __fdividef(ss - 1.0f, c2); k = kn; }
            }
            if (sl == 0) tau_time[task] = tau;
        }
    }

    // ---- Phase B: instrument sparsemax (sort-based, branch-free).
    //      Depends only on xs (already synced) -> runs BEFORE the barrier so
    //      the Phase-A skew is hidden under this compute. ----
    const int t0 = tid * 2;                  // 2 adjacent columns
    float ta, tb2;
    {
        float za[NI], zb[NI];
        #pragma unroll
        for (int i = 0; i < NI; ++i) {
            const float2 v = *(const float2*)(xs + i * CHUNK + t0);
            za[i] = v.x; zb[i] = v.y;
        }
        ta  = sparsemax11_tau(za);           // destroys za
        tb2 = sparsemax11_tau(zb);           // destroys zb
    }

    __syncthreads();                         // tau_time now visible

    // ---- Phase C: fused epilogue straight to gmem ----
    {
        const int blkb = wid;                // t0>>6 == tid>>5 (uniform/warp)
        const float* px = xs + t0;
        float* po = out + base + (unsigned)t0;
        #pragma unroll
        for (int i = 0; i < NI; ++i) {
            const float  tt = tau_time[i * NTB + blkb];  // broadcast LDS
            const float2 v  = *(const float2*)(px + i * CHUNK);
            float2 r;
            r.x = fmaxf(v.x - ta,  0.0f) * fmaxf(v.x - tt, 0.0f);
            r.y = fmaxf(v.y - tb2, 0.0f) * fmaxf(v.y - tt, 0.0f);
            *(float2*)(po + (unsigned)(i * NT)) = r;
        }
    }
}

extern "C" void kernel_launch(void* const* d_in, const int* in_sizes, int n_in,
                              void* d_out, int out_size)
{
    const float* in = (const float*)d_in[0];
    float* out = (float*)d_out;
    multiply_sparsemax_kernel<<<NB * NCHUNK, THREADS>>>(in, out);
}